// round 11
// baseline (speedup 1.0000x reference)
#include <cuda_runtime.h>
#include <cuda_fp16.h>
#include <cstdint>

#define TOKENS    16384
#define DDIM      2048
#define NEXP      64
#define MTILE     128
#define NBLK      (TOKENS / MTILE)       // 128
#define KC        64                     // K floats per chunk
#define NCHUNK    (DDIM / KC)            // 32
#define XROWB     288                    // x fp32 row stride (bytes): bank-safe
#define XBYTES    (MTILE * XROWB)        // 36864
#define WROWB     144                    // W fp16 plane row stride (bytes)
#define WPBYTES   (NEXP * WROWB)         // 9216 per plane
#define STAGE     (XBYTES + 2 * WPBYTES) // 55296
#define SMEM_BYTES (2 * STAGE)           // 110592
#define EPIPITCH  68                     // floats; epilogue smem pitch
#define IDX_COUNT (TOKENS * 2)
#define LO_SCALE  2048.0f
#define LO_INV    (1.0f / 2048.0f)

__device__ float g_partials[NBLK * NEXP];

// ---------------- PTX helpers (base sm_103-safe) ----------------
__device__ __forceinline__ uint32_t smem_u32(const void* p) {
    uint32_t a;
    asm("{ .reg .u64 t; cvta.to.shared.u64 t, %1; cvt.u32.u64 %0, t; }" : "=r"(a) : "l"(p));
    return a;
}
__device__ __forceinline__ void cpa16(uint32_t dst, const void* src) {
    asm volatile("cp.async.cg.shared.global [%0], [%1], 16;" :: "r"(dst), "l"(src) : "memory");
}
__device__ __forceinline__ void cpa_commit() {
    asm volatile("cp.async.commit_group;" ::: "memory");
}
__device__ __forceinline__ void cpa_wait1() {
    asm volatile("cp.async.wait_group 1;" ::: "memory");
}
__device__ __forceinline__ void ldsm_x4(uint32_t* r, uint32_t addr) {
    asm volatile("ldmatrix.sync.aligned.m8n8.x4.shared.b16 {%0,%1,%2,%3}, [%4];"
                 : "=r"(r[0]), "=r"(r[1]), "=r"(r[2]), "=r"(r[3]) : "r"(addr));
}
__device__ __forceinline__ void lds64(float2& v, uint32_t addr) {
    asm volatile("ld.shared.v2.f32 {%0,%1}, [%2];" : "=f"(v.x), "=f"(v.y) : "r"(addr));
}
__device__ __forceinline__ void sts128(uint32_t a, uint32_t x, uint32_t y,
                                       uint32_t z, uint32_t w) {
    asm volatile("st.shared.v4.b32 [%0], {%1,%2,%3,%4};"
                 :: "r"(a), "r"(x), "r"(y), "r"(z), "r"(w) : "memory");
}
__device__ __forceinline__ void mma_f16(float* d, const uint32_t* a, const uint32_t* b) {
    asm volatile(
        "mma.sync.aligned.m16n8k16.row.col.f32.f16.f16.f32 "
        "{%0,%1,%2,%3}, {%4,%5,%6,%7}, {%8,%9}, {%0,%1,%2,%3};"
        : "+f"(d[0]), "+f"(d[1]), "+f"(d[2]), "+f"(d[3])
        : "r"(a[0]), "r"(a[1]), "r"(a[2]), "r"(a[3]), "r"(b[0]), "r"(b[1]));
}
// split float2 -> packed fp16 hi + packed fp16 lo*2048 (tf32-class precision)
__device__ __forceinline__ void split_f16(float2 v, uint32_t& hi, uint32_t& lo) {
    __half2 h = __float22half2_rn(v);
    float2  hf = __half22float2(h);
    __half2 l = __float22half2_rn(
        make_float2((v.x - hf.x) * LO_SCALE, (v.y - hf.y) * LO_SCALE));
    hi = *reinterpret_cast<uint32_t*>(&h);
    lo = *reinterpret_cast<uint32_t*>(&l);
}

// ============================================================================
// K1: fused 3xFP16 (hi/lo) mma.sync GEMM + per-token top-2/softmax epilogue.
// 128 blocks x 256 threads; tile M=128 x N=64 x K=2048, KC=64 per chunk.
// x staged raw via cp.async (A split in regs); W LDG'd raw fp32 (L2-resident),
// split in regs during staging (register-prefetched one chunk ahead), STS'd
// as fp16 hi/lo planes. accH += Ah*Bh ; accL += Ah*Bl' + Al'*Bh.
// ============================================================================
__global__ __launch_bounds__(256)
void k1_fused(const float* __restrict__ x, const float* __restrict__ W,
              float* __restrict__ out, int out_size) {
    extern __shared__ char dsm[];
    const int tid  = threadIdx.x;
    const int lane = tid & 31;
    const int w    = tid >> 5;
    const int tok0 = blockIdx.x * MTILE;
    const uint32_t sb = smem_u32(dsm);

    // x cp.async descriptors: 128 rows x 16 float4 per chunk; 8 per thread
    const float* xsrc[8]; uint32_t xdst[8];
#pragma unroll
    for (int i = 0; i < 8; i++) {
        int f = tid + 256 * i, row = f >> 4, c4 = f & 15;
        xsrc[i] = x + (size_t)(tok0 + row) * DDIM + c4 * 4;
        xdst[i] = (uint32_t)(row * XROWB + c4 * 16);
    }
    // W staging: thread owns row = tid>>2 (0..63), quarter qc = tid&3 (16 floats)
    const int wrow = tid >> 2, wqc = tid & 3;
    const float* wsrc = W + (size_t)wrow * DDIM + wqc * 16;
    const uint32_t whidst = (uint32_t)(XBYTES + wrow * WROWB + wqc * 32);

    // A LDS.64 base: row = w*16 + lane/4, col pair (lane%4)*2
    const uint32_t abase = (uint32_t)((w * 16 + (lane >> 2)) * XROWB + (lane & 3) * 8);
    // B ldmatrix lane offset within a plane
    const int brow = lane & 7, bsel = lane >> 3;
    const uint32_t blaneoff =
        (uint32_t)((brow + (bsel >> 1) * 8) * WROWB + (bsel & 1) * 16);

    float accH[8][4], accL[8][4];
#pragma unroll
    for (int n = 0; n < 8; n++)
#pragma unroll
        for (int r = 0; r < 4; r++) { accH[n][r] = 0.0f; accL[n][r] = 0.0f; }

    float4 wreg[4];   // W prefetch registers (16 floats)

    // ---- Prologue ----
    // x chunks 0,1 via cp.async (one commit group per chunk)
#pragma unroll
    for (int st = 0; st < 2; st++) {
        const uint32_t B = sb + st * STAGE;
#pragma unroll
        for (int i = 0; i < 8; i++) cpa16(B + xdst[i], xsrc[i] + st * KC);
        cpa_commit();
    }
    // W chunks 0,1: LDG -> split -> STS (synchronous, prologue only)
#pragma unroll
    for (int st = 0; st < 2; st++) {
        const uint32_t B = sb + st * STAGE;
#pragma unroll
        for (int q = 0; q < 4; q++)
            wreg[q] = *reinterpret_cast<const float4*>(wsrc + st * KC + q * 4);
        uint32_t h[8], l[8];
#pragma unroll
        for (int q = 0; q < 4; q++) {
            split_f16(make_float2(wreg[q].x, wreg[q].y), h[2 * q],     l[2 * q]);
            split_f16(make_float2(wreg[q].z, wreg[q].w), h[2 * q + 1], l[2 * q + 1]);
        }
        sts128(B + whidst,      h[0], h[1], h[2], h[3]);
        sts128(B + whidst + 16, h[4], h[5], h[6], h[7]);
        sts128(B + whidst + WPBYTES,      l[0], l[1], l[2], l[3]);
        sts128(B + whidst + WPBYTES + 16, l[4], l[5], l[6], l[7]);
    }
    // prefetch W chunk 2 into regs
#pragma unroll
    for (int q = 0; q < 4; q++)
        wreg[q] = *reinterpret_cast<const float4*>(wsrc + 2 * KC + q * 4);

    for (int c = 0; c < NCHUNK; c++) {
        cpa_wait1();
        __syncthreads();

        const uint32_t XS = sb + (c & 1) * STAGE;
        const uint32_t WH = XS + XBYTES;
        const uint32_t WL = WH + WPBYTES;

#pragma unroll
        for (int ks = 0; ks < 4; ks++) {          // four k16 steps per k64 chunk
            // A fragments: fp32 x at fragment positions -> fp16 split in regs
            uint32_t Ah[4], Al[4];
            {
                const uint32_t ab = XS + abase + ks * 64;
                float2 v00, v10, v01, v11;
                lds64(v00, ab);
                lds64(v10, ab + 8 * XROWB);
                lds64(v01, ab + 32);
                lds64(v11, ab + 8 * XROWB + 32);
                split_f16(v00, Ah[0], Al[0]);
                split_f16(v10, Ah[1], Al[1]);
                split_f16(v01, Ah[2], Al[2]);
                split_f16(v11, Ah[3], Al[3]);
            }
            // B fragments: fp16 hi/lo planes via ldmatrix
            uint32_t Bh[8][2], Bl[8][2];
#pragma unroll
            for (int np = 0; np < 4; np++) {
                uint32_t t[4];
                ldsm_x4(t, WH + (uint32_t)(np * 16 * WROWB + ks * 32) + blaneoff);
                Bh[2 * np][0] = t[0]; Bh[2 * np][1] = t[1];
                Bh[2 * np + 1][0] = t[2]; Bh[2 * np + 1][1] = t[3];
                ldsm_x4(t, WL + (uint32_t)(np * 16 * WROWB + ks * 32) + blaneoff);
                Bl[2 * np][0] = t[0]; Bl[2 * np][1] = t[1];
                Bl[2 * np + 1][0] = t[2]; Bl[2 * np + 1][1] = t[3];
            }
#pragma unroll
            for (int n = 0; n < 8; n++) {
                mma_f16(accH[n], Ah, Bh[n]);
                mma_f16(accL[n], Ah, Bl[n]);
                mma_f16(accL[n], Al, Bh[n]);
            }
        }

        __syncthreads();
        // stage chunk c+2 into the freed buffer
        if (c + 2 < NCHUNK) {
            const uint32_t B = sb + (c & 1) * STAGE;
            const int o = (c + 2) * KC;
#pragma unroll
            for (int i = 0; i < 8; i++) cpa16(B + xdst[i], xsrc[i] + o);
            // W: split prefetched regs -> STS
            uint32_t h[8], l[8];
#pragma unroll
            for (int q = 0; q < 4; q++) {
                split_f16(make_float2(wreg[q].x, wreg[q].y), h[2 * q],     l[2 * q]);
                split_f16(make_float2(wreg[q].z, wreg[q].w), h[2 * q + 1], l[2 * q + 1]);
            }
            sts128(B + whidst,      h[0], h[1], h[2], h[3]);
            sts128(B + whidst + 16, h[4], h[5], h[6], h[7]);
            sts128(B + whidst + WPBYTES,      l[0], l[1], l[2], l[3]);
            sts128(B + whidst + WPBYTES + 16, l[4], l[5], l[6], l[7]);
        }
        cpa_commit();
        // prefetch W regs for chunk c+3 (latency hidden under next compute)
        if (c + 3 < NCHUNK) {
            const int o = (c + 3) * KC;
#pragma unroll
            for (int q = 0; q < 4; q++)
                wreg[q] = *reinterpret_cast<const float4*>(wsrc + o + q * 4);
        }
    }
    __syncthreads();

    // ---- fused epilogue ----
    // 1) combine hi/lo accumulators -> smem logits [128][EPIPITCH] (34 KB)
    float* lgs = reinterpret_cast<float*>(dsm);
    {
        const int r0 = w * 16 + (lane >> 2);
        const int cb = (lane & 3) * 2;
#pragma unroll
        for (int n = 0; n < 8; n++) {
            const int col = n * 8 + cb;
            *reinterpret_cast<float2*>(lgs + r0 * EPIPITCH + col) =
                make_float2(accH[n][0] + accL[n][0] * LO_INV,
                            accH[n][1] + accL[n][1] * LO_INV);
            *reinterpret_cast<float2*>(lgs + (r0 + 8) * EPIPITCH + col) =
                make_float2(accH[n][2] + accL[n][2] * LO_INV,
                            accH[n][3] + accL[n][3] * LO_INV);
        }
    }
    __syncthreads();

    // 2) one thread per TOKEN: top-2 + softmax + outputs + prob row
    if (tid < MTILE) {
        float* row = lgs + tid * EPIPITCH;
        float lg[64];
#pragma unroll
        for (int e = 0; e < NEXP; e++) lg[e] = row[e];

        float v1 = -1e30f, v2 = -1e30f; int j1 = 0, j2 = 0;
#pragma unroll
        for (int e = 0; e < NEXP; e++) {
            float l = lg[e];
            if (l > v1)      { v2 = v1; j2 = j1; v1 = l; j1 = e; }
            else if (l > v2) { v2 = l;  j2 = e; }
        }
        float s = 0.0f;
#pragma unroll
        for (int e = 0; e < NEXP; e++) { float p = __expf(lg[e] - v1); lg[e] = p; s += p; }
        const float inv = 1.0f / s;

        const int t = tok0 + tid;
        out[t * 2]                 = (float)j1;
        out[t * 2 + 1]             = (float)j2;
        const float w1 = 1.0f / (1.0f + __expf(v2 - v1));
        out[IDX_COUNT + t * 2]     = w1;
        out[IDX_COUNT + t * 2 + 1] = 1.0f - w1;

#pragma unroll
        for (int e = 0; e < NEXP; e++) row[e] = lg[e] * inv;
    }
    __syncthreads();

    // 3) deterministic per-block usage partials
    if (tid < NEXP) {
        float u = 0.0f;
        for (int r = 0; r < MTILE; r++) u += lgs[r * EPIPITCH + tid];
        g_partials[blockIdx.x * NEXP + tid] = u;
    }
}

// ============================================================================
// K3: aux loss. 512 threads, 8-way partition, two-level deterministic reduce.
// ============================================================================
__global__ __launch_bounds__(512)
void k3_aux(float* __restrict__ out, int out_size) {
    __shared__ float red[512];
    const int tid  = threadIdx.x;
    const int e    = tid & 63;
    const int part = tid >> 6;

    float s = 0.0f;
#pragma unroll
    for (int i = 0; i < NBLK / 8; i++)
        s += g_partials[(part + 8 * i) * NEXP + e];
    red[tid] = s;
    __syncthreads();

    if (tid < NEXP) {
        float u = 0.0f;
#pragma unroll
        for (int p = 0; p < 8; p++) u += red[p * 64 + tid];
        float d = u * (1.0f / (float)TOKENS) - (1.0f / (float)NEXP);
        red[tid] = d * d;
    }
    __syncthreads();

    if (tid == 0) {
        float a = 0.0f;
#pragma unroll
        for (int i = 0; i < NEXP; i++) a += red[i];
        if (out_size > 2 * IDX_COUNT) out[out_size - 1] = a;
    }
}

// ============================================================================
extern "C" void kernel_launch(void* const* d_in, const int* in_sizes, int n_in,
                              void* d_out, int out_size) {
    const float* x = (const float*)d_in[0];   // [16384, 2048]
    const float* W = (const float*)d_in[1];   // [64, 2048]
    float* out = (float*)d_out;

    cudaFuncSetAttribute(k1_fused, cudaFuncAttributeMaxDynamicSharedMemorySize, SMEM_BYTES);

    k1_fused<<<NBLK, 256, SMEM_BYTES>>>(x, W, out, out_size);
    k3_aux<<<1, 512>>>(out, out_size);
}